// round 16
// baseline (speedup 1.0000x reference)
#include <cuda_runtime.h>
#include <cuda_bf16.h>
#include <cuda_fp16.h>
#include <cstdint>

// ============================================================================
// Problem constants
// ============================================================================
#define NROWS 16384
#define DDIM  128
#define TILE  128
#define NJOBS 16384              // 128 row-blocks x 128 col-tiles

static __device__ __nv_bfloat16 g_Abf[NROWS * DDIM];  // normalized * C_EXP
static __device__ __nv_bfloat16 g_Pbf[NROWS * DDIM];  // normalized
static __device__ float g_partS[NROWS];   // per-row expsum (atomic-accumulated)
static __device__ float g_diagv[NROWS];   // C_EXP * diag dot (log2 units)
static __device__ unsigned g_done;        // worker completion counter

#define C_EXP   20.609929155556620f   // log2(e)/0.07, folded into A
#define LN2     0.69314718055994531f  // diag: dot/T = (C_EXP*dot)*ln2

// SMEM: 3 rotating 128x128 bf16 slabs (272B padded rows) + mbarrier block.
// Slab index 2 (@0) holds the A tile at segment start, then rejoins the B
// rotation (A frags live in regs). Tile t lives in buffer (t % 3).
#define ROWB   272
#define SLAB   34816
#define BAR_OFF (3 * 34816)
#define SMEM_TOTAL (3 * 34816 + 128)

// ============================================================================
// PTX helpers (no arch-suffixed features; ptxas target is plain sm_100)
// ============================================================================
__device__ __forceinline__ uint32_t smem_to_u32(const void* p) {
    uint32_t a;
    asm("{ .reg .u64 t; cvta.to.shared.u64 t, %1; cvt.u32.u64 %0, t; }" : "=r"(a) : "l"(p));
    return a;
}
__device__ __forceinline__ float ex2f_fast(float x) {
    float y; asm("ex2.approx.ftz.f32 %0, %1;" : "=f"(y) : "f"(x)); return y;
}
__device__ __forceinline__ float lg2f_fast(float x) {
    float y; asm("lg2.approx.f32 %0, %1;" : "=f"(y) : "f"(x)); return y;
}
// f16x2 epilogue ops: pack 2 f32, one MUFU exp2 for both halves, f16x2 add
__device__ __forceinline__ uint32_t cvt_f16x2(float a, float b) {
    uint32_t r; asm("cvt.rn.f16x2.f32 %0, %1, %2;" : "=r"(r) : "f"(b), "f"(a)); return r;
}
__device__ __forceinline__ uint32_t ex2_f16x2(uint32_t x) {
    uint32_t y; asm("ex2.approx.f16x2 %0, %1;" : "=r"(y) : "r"(x)); return y;
}
__device__ __forceinline__ uint32_t hadd2(uint32_t a, uint32_t b) {
    uint32_t r; asm("add.f16x2 %0, %1, %2;" : "=r"(r) : "r"(a), "r"(b)); return r;
}
__device__ __forceinline__ float h2sum(uint32_t h) {
    __half2 v = *reinterpret_cast<__half2*>(&h);
    float2 f = __half22float2(v);
    return f.x + f.y;
}

#define LDSM_X4(r0, r1, r2, r3, addr) \
    asm volatile("ldmatrix.sync.aligned.m8n8.x4.shared.b16 {%0,%1,%2,%3}, [%4];" \
        : "=r"(r0), "=r"(r1), "=r"(r2), "=r"(r3) : "r"(addr))

#define MMA_BF16(d, a, b0, b1) \
    asm volatile("mma.sync.aligned.m16n8k16.row.col.f32.bf16.bf16.f32 " \
        "{%0,%1,%2,%3},{%4,%5,%6,%7},{%8,%9},{%0,%1,%2,%3};" \
        : "+f"((d)[0]), "+f"((d)[1]), "+f"((d)[2]), "+f"((d)[3]) \
        : "r"((a)[0]), "r"((a)[1]), "r"((a)[2]), "r"((a)[3]), "r"(b0), "r"(b1))

#define CP_ASYNC16(saddr, gptr) \
    asm volatile("cp.async.cg.shared.global [%0], [%1], 16;" :: "r"(saddr), "l"(gptr))
#define CP_COMMIT() asm volatile("cp.async.commit_group;")
#define CP_WAIT2()  asm volatile("cp.async.wait_group 2;")
// hardware arrival: fires on the mbarrier once all prior cp.async of this
// thread have completed (no wait instruction needed)
#define CP_ASYNC_MBAR_ARRIVE(a) \
    asm volatile("cp.async.mbarrier.arrive.noinc.shared.b64 [%0];" :: "r"(a) : "memory")

#define MBAR_INVAL(a) \
    asm volatile("mbarrier.inval.shared.b64 [%0];" :: "r"(a) : "memory")
#define MBAR_INIT(a, cnt) \
    asm volatile("mbarrier.init.shared.b64 [%0], %1;" :: "r"(a), "r"(cnt) : "memory")
#define MBAR_ARRIVE(a) \
    asm volatile("{.reg .b64 s; mbarrier.arrive.release.cta.shared::cta.b64 s, [%0];}" \
        :: "r"(a) : "memory")
#define MBAR_WAIT(a, par) do { \
    uint32_t _done; \
    asm volatile("{\n\t.reg .pred p;\n\t" \
        "mbarrier.try_wait.parity.acquire.cta.shared::cta.b64 p, [%1], %2;\n\t" \
        "selp.b32 %0, 1, 0, p;\n\t}" : "=r"(_done) : "r"(a), "r"(par) : "memory"); \
    while (!_done) { \
        asm volatile("{\n\t.reg .pred p;\n\t" \
            "mbarrier.try_wait.parity.acquire.cta.shared::cta.b64 p, [%1], %2;\n\t" \
            "selp.b32 %0, 1, 0, p;\n\t}" : "=r"(_done) : "r"(a), "r"(par) : "memory"); \
    } \
} while (0)

// warp-elected arrive: one smem atomic per warp instead of 32
#define WARP_ARRIVE(a, lane) do { \
    __syncwarp(); \
    if ((lane) == 0) MBAR_ARRIVE(a); \
} while (0)

// ============================================================================
// Kernel 1: normalize rows (fp32) -> bf16 (A scaled by C_EXP); zero state
// ============================================================================
__global__ void __launch_bounds__(256) normalize_kernel(const float* __restrict__ A,
                                                        const float* __restrict__ P) {
    int gid = blockIdx.x * blockDim.x + threadIdx.x;
    if (gid == 0) g_done = 0u;
    if (gid < NROWS) g_partS[gid] = 0.0f;
    int warp = gid >> 5;
    int lane = threadIdx.x & 31;
    if (warp >= 2 * NROWS) return;
    const float* src;
    __nv_bfloat16* dst;
    float extra;
    if (warp < NROWS) {
        src = A + (size_t)warp * DDIM; dst = g_Abf + (size_t)warp * DDIM; extra = C_EXP;
    } else {
        int r = warp - NROWS;
        src = P + (size_t)r * DDIM; dst = g_Pbf + (size_t)r * DDIM; extra = 1.0f;
    }
    float4 v = reinterpret_cast<const float4*>(src)[lane];
    float ss = v.x * v.x + v.y * v.y + v.z * v.z + v.w * v.w;
    #pragma unroll
    for (int o = 16; o > 0; o >>= 1) ss += __shfl_xor_sync(0xFFFFFFFFu, ss, o);
    float s = extra / fmaxf(sqrtf(ss), 1e-12f);
    __nv_bfloat162 h0 = __floats2bfloat162_rn(v.x * s, v.y * s);
    __nv_bfloat162 h1 = __floats2bfloat162_rn(v.z * s, v.w * s);
    reinterpret_cast<__nv_bfloat162*>(dst)[lane * 2 + 0] = h0;
    reinterpret_cast<__nv_bfloat162*>(dst)[lane * 2 + 1] = h1;
}

// ============================================================================
// cp.async loader: 128x128 bf16 tile (row-major) -> padded SMEM (272B rows)
// ============================================================================
__device__ __forceinline__ void cp_tile(uint32_t sbase, const __nv_bfloat16* gsrc, int tid) {
    const char* g = reinterpret_cast<const char*>(gsrc);
    #pragma unroll
    for (int i = 0; i < 8; i++) {
        int idx = tid + i * 256;          // 2048 chunks of 16B
        int row = idx >> 4;
        int c   = idx & 15;
        uint32_t s = sbase + row * ROWB + c * 16;
        CP_ASYNC16(s, g + idx * 16);
    }
}

// ============================================================================
// Kernel 2: persistent fused GEMM + exp rowsum + diag + last-block reduction.
// R13 pipeline (hw cp-completion full arrivals, warp-elected empties,
// chunk-3 deferral). Non-diag tiles use an ex2.approx.f16x2 epilogue
// (2 exps / MUFU op -> MUFU pipe load halved); the <=1 diag tile per
// segment keeps the f32 epilogue (diag element 2^20.6 overflows f16).
// ============================================================================
__global__ void __launch_bounds__(256, 2) infonce_main_kernel(float* __restrict__ out) {
    extern __shared__ char smem[];
    uint32_t sb = smem_to_u32(smem);
    int tid = threadIdx.x;
    int lane = tid & 31;
    int w = tid >> 5;
    int wr = w >> 1;            // row-group 0..3 (32 rows)
    int wc = w & 1;             // col-group 0..1 (64 cols)

    int G = gridDim.x;
    int j0 = (int)(((long long)blockIdx.x * NJOBS) / G);
    int j1 = (int)(((long long)(blockIdx.x + 1) * NJOBS) / G);

    int g = lane >> 2;
    int tig = lane & 3;
    uint32_t b_lane_off = (uint32_t)(((lane & 7) + ((lane >> 4) << 3)) * ROWB
                                     + ((lane >> 3) & 1) * 16)
                          + (uint32_t)(wc * 64) * ROWB;
    // tile t -> buffer t%3; buffer i at bufoff[i]. Buffer 2 = A slab (@0).
    const uint32_t bufoff[3] = {SLAB, 2 * SLAB, 0};
    uint32_t bfull[3], bempty[3];
    #pragma unroll
    for (int i = 0; i < 3; i++) {
        bfull[i]  = sb + BAR_OFF + i * 8;
        bempty[i] = sb + BAR_OFF + 24 + i * 8;
    }

    int j = j0;
    while (j < j1) {
        int rb = j >> 7;
        int c0 = j & 127;
        int cend = min(j1 - (rb << 7), 128);
        int nt = cend - c0;

        __syncthreads();   // previous segment fully done with smem
        if (tid == 0) {
            #pragma unroll
            for (int i = 0; i < 3; i++) {
                MBAR_INVAL(bfull[i]);  MBAR_INIT(bfull[i], 256u);  // hw cp arrivals
                MBAR_INVAL(bempty[i]); MBAR_INIT(bempty[i], 8u);   // warp-elected
            }
        }
        __syncthreads();   // barriers initialized

        // Prologue: A -> slab (buffer 2), then tiles c0/c0+1 with hw arrivals
        cp_tile(sb + bufoff[2], g_Abf + (size_t)rb * TILE * DDIM, tid);
        CP_COMMIT();                       // group: A
        cp_tile(sb + bufoff[0], g_Pbf + (size_t)c0 * TILE * DDIM, tid);
        CP_ASYNC_MBAR_ARRIVE(bfull[0]);
        CP_COMMIT();                       // group: tile 0
        if (nt > 1) {
            cp_tile(sb + bufoff[1], g_Pbf + (size_t)(c0 + 1) * TILE * DDIM, tid);
            CP_ASYNC_MBAR_ARRIVE(bfull[1]);
        }
        CP_COMMIT();                       // group: tile 1 (possibly empty)
        CP_WAIT2();        // A group done locally (tiles 0/1 may pend)
        __syncthreads();   // A visible to all threads

        // A fragments: 8 k-steps x 2 m16-frags x 4 regs
        uint32_t afrag[8][2][4];
        #pragma unroll
        for (int f = 0; f < 2; f++) {
            uint32_t a_addr = sb + bufoff[2] + (wr * 32 + f * 16 + (lane & 15)) * ROWB
                              + (lane >> 4) * 16;
            #pragma unroll
            for (int k = 0; k < 8; k++)
                LDSM_X4(afrag[k][f][0], afrag[k][f][1], afrag[k][f][2], afrag[k][f][3],
                        a_addr + k * 32);
        }
        WARP_ARRIVE(bempty[2], lane);   // frag-load = buffer 2's gen-0 consumption

        float S[4] = {0.f, 0.f, 0.f, 0.f};
        float d[4] = {0.f, 0.f, 0.f, 0.f};

        for (int t = 0; t < nt; t++) {
            int buf = t % 3;
            uint32_t par = (uint32_t)((t / 3) & 1);
            MBAR_WAIT(bfull[buf], par);      // tile t landed (hw arrivals)

            uint32_t bbase = sb + bufoff[buf] + b_lane_off;
            int diag_t = (c0 + t == rb);
            float pend[16];
            uint32_t hS[4] = {0u, 0u, 0u, 0u};

            if (!diag_t) {
                // ---- fast path: f16x2 epilogue (2 exps per MUFU op) ----
                #pragma unroll
                for (int c = 0; c < 3; c++) {
                    float acc[16];
                    #pragma unroll
                    for (int q = 0; q < 16; q++) acc[q] = 0.0f;
                    uint32_t bchunk = bbase + (uint32_t)(c * 16) * ROWB;
                    #pragma unroll
                    for (int k = 0; k < 8; k++) {
                        uint32_t b0, b1, b2, b3;
                        LDSM_X4(b0, b1, b2, b3, bchunk + k * 32);
                        MMA_BF16(acc + 0,  afrag[k][0], b0, b1);
                        MMA_BF16(acc + 4,  afrag[k][0], b2, b3);
                        MMA_BF16(acc + 8,  afrag[k][1], b0, b1);
                        MMA_BF16(acc + 12, afrag[k][1], b2, b3);
                    }
                    #pragma unroll
                    for (int f = 0; f < 2; f++)
                        #pragma unroll
                        for (int nb = 0; nb < 2; nb++) {
                            const float* a4 = acc + f * 8 + nb * 4;
                            hS[f * 2 + 0] = hadd2(hS[f * 2 + 0],
                                                  ex2_f16x2(cvt_f16x2(a4[0], a4[1])));
                            hS[f * 2 + 1] = hadd2(hS[f * 2 + 1],
                                                  ex2_f16x2(cvt_f16x2(a4[2], a4[3])));
                        }
                }
                // chunk 3: MMA only; epilogue deferred past producer ops
                #pragma unroll
                for (int q = 0; q < 16; q++) pend[q] = 0.0f;
                uint32_t bchunk = bbase + (uint32_t)(3 * 16) * ROWB;
                #pragma unroll
                for (int k = 0; k < 8; k++) {
                    uint32_t b0, b1, b2, b3;
                    LDSM_X4(b0, b1, b2, b3, bchunk + k * 32);
                    MMA_BF16(pend + 0,  afrag[k][0], b0, b1);
                    MMA_BF16(pend + 4,  afrag[k][0], b2, b3);
                    MMA_BF16(pend + 8,  afrag[k][1], b0, b1);
                    MMA_BF16(pend + 12, afrag[k][1], b2, b3);
                }
            } else {
                // ---- diag tile: f32 epilogue + capture (no f16 overflow) ----
                #pragma unroll
                for (int c = 0; c < 4; c++) {
                    float acc[16];
                    #pragma unroll
                    for (int q = 0; q < 16; q++) acc[q] = 0.0f;
                    uint32_t bchunk = bbase + (uint32_t)(c * 16) * ROWB;
                    #pragma unroll
                    for (int k = 0; k < 8; k++) {
                        uint32_t b0, b1, b2, b3;
                        LDSM_X4(b0, b1, b2, b3, bchunk + k * 32);
                        MMA_BF16(acc + 0,  afrag[k][0], b0, b1);
                        MMA_BF16(acc + 4,  afrag[k][0], b2, b3);
                        MMA_BF16(acc + 8,  afrag[k][1], b0, b1);
                        MMA_BF16(acc + 12, afrag[k][1], b2, b3);
                    }
                    #pragma unroll
                    for (int f = 0; f < 2; f++)
                        #pragma unroll
                        for (int nb = 0; nb < 2; nb++)
                            #pragma unroll
                            for (int q = 0; q < 4; q++) {
                                float v = acc[f * 8 + nb * 4 + q];
                                int hi = q >> 1;
                                S[f * 2 + hi] += ex2f_fast(v);
                                int col_local = wc * 64 + c * 16 + nb * 8 + tig * 2 + (q & 1);
                                int row_local = wr * 32 + f * 16 + hi * 8 + g;
                                if (col_local == row_local) d[f * 2 + hi] = v;
                            }
                }
            }
            WARP_ARRIVE(bempty[buf], lane);  // this warp's LDSMs of tile t done

            // producer (all warps share): tile t+2 into buffer (t+2)%3
            if (t + 2 < nt) {
                int wbuf = (t + 2) % 3;
                MBAR_WAIT(bempty[wbuf], par);   // same (t/3)&1 parity
                cp_tile(sb + bufoff[wbuf], g_Pbf + (size_t)(c0 + t + 2) * TILE * DDIM, tid);
                CP_ASYNC_MBAR_ARRIVE(bfull[wbuf]);  // hw arrival when copies land
            }

            // deferred chunk-3 f16x2 epilogue + per-tile flush of hS into S
            if (!diag_t) {
                #pragma unroll
                for (int f = 0; f < 2; f++)
                    #pragma unroll
                    for (int nb = 0; nb < 2; nb++) {
                        const float* a4 = pend + f * 8 + nb * 4;
                        hS[f * 2 + 0] = hadd2(hS[f * 2 + 0],
                                              ex2_f16x2(cvt_f16x2(a4[0], a4[1])));
                        hS[f * 2 + 1] = hadd2(hS[f * 2 + 1],
                                              ex2_f16x2(cvt_f16x2(a4[2], a4[3])));
                    }
                #pragma unroll
                for (int i = 0; i < 4; i++) S[i] += h2sum(hS[i]);
            }
        }

        // segment flush: reduce across the 4 threads sharing each row
        #pragma unroll
        for (int i = 0; i < 4; i++) {
            S[i] += __shfl_xor_sync(0xFFFFFFFFu, S[i], 1);
            S[i] += __shfl_xor_sync(0xFFFFFFFFu, S[i], 2);
            d[i] += __shfl_xor_sync(0xFFFFFFFFu, d[i], 1);
            d[i] += __shfl_xor_sync(0xFFFFFFFFu, d[i], 2);
        }
        if (tig == 0) {
            int seg_has_diag = (rb >= c0) && (rb < cend);
            int wrote_diag = seg_has_diag && ((wr >> 1) == wc);
            #pragma unroll
            for (int i = 0; i < 4; i++) {
                int row_local = wr * 32 + (i >> 1) * 16 + (i & 1) * 8 + g;
                int row = rb * TILE + row_local;
                atomicAdd(&g_partS[row], S[i]);
                if (wrote_diag) g_diagv[row] = d[i];
            }
        }
        j += nt;
    }

    // ---------------- last-block reduction: rowsum + finalize --------------
    __threadfence();
    __shared__ unsigned s_islast;
    __syncthreads();
    if (tid == 0) {
        unsigned t = atomicAdd(&g_done, 1u);
        s_islast = (t == (unsigned)(G - 1)) ? 1u : 0u;
    }
    __syncthreads();
    if (s_islast) {
        float sum = 0.0f;
        for (int row = tid; row < NROWS; row += 256) {
            float ps = __ldcg(&g_partS[row]);
            float dv = __ldcg(&g_diagv[row]);
            sum += (lg2f_fast(ps) - dv) * LN2;
        }
        #pragma unroll
        for (int o = 16; o > 0; o >>= 1) sum += __shfl_xor_sync(0xFFFFFFFFu, sum, o);
        __shared__ float red[8];
        if (lane == 0) red[w] = sum;
        __syncthreads();
        if (w == 0) {
            float s2 = (lane < 8) ? red[lane] : 0.0f;
            #pragma unroll
            for (int o = 4; o > 0; o >>= 1) s2 += __shfl_xor_sync(0xFFFFFFFFu, s2, o);
            if (lane == 0) out[0] = s2 * (1.0f / (float)NROWS);
        }
    }
}

// ============================================================================
// Launch
// ============================================================================
extern "C" void kernel_launch(void* const* d_in, const int* in_sizes, int n_in,
                              void* d_out, int out_size) {
    const float* A = (const float*)d_in[0];
    const float* P = (const float*)d_in[1];
    int nsm = 148;
    cudaDeviceGetAttribute(&nsm, cudaDevAttrMultiProcessorCount, 0);
    cudaFuncSetAttribute(infonce_main_kernel,
                         cudaFuncAttributeMaxDynamicSharedMemorySize, SMEM_TOTAL);
    normalize_kernel<<<(2 * NROWS) / 8, 256>>>(A, P);
    infonce_main_kernel<<<2 * nsm, 256, SMEM_TOTAL>>>((float*)d_out);
}

// round 17
// speedup vs baseline: 1.0976x; 1.0976x over previous
#include <cuda_runtime.h>
#include <cuda_bf16.h>
#include <cstdint>

// ============================================================================
// Problem constants
// ============================================================================
#define NROWS 16384
#define DDIM  128
#define TILE  128
#define SUPER 256                 // rows per CTA super-tile
#define NJOBS 8192                // 64 super-rows x 128 col-tiles

static __device__ __nv_bfloat16 g_Abf[NROWS * DDIM];  // normalized * C_EXP
static __device__ __nv_bfloat16 g_Pbf[NROWS * DDIM];  // normalized
static __device__ float g_partS[NROWS];   // per-row expsum (atomic-accumulated)
static __device__ float g_diagv[NROWS];   // C_EXP * diag dot (log2 units)
static __device__ unsigned g_done;        // worker completion counter

#define C_EXP   20.609929155556620f   // log2(e)/0.07, folded into A
#define LN2     0.69314718055994531f  // diag: dot/T = (C_EXP*dot)*ln2

// SMEM: 3 rotating 128x128 bf16 slabs (272B padded rows) + mbarrier block.
// A (256 rows) loads into slabs 1+2 at segment start (frags -> regs), then
// both rejoin the 3-deep B ring. Tile t lives in buffer (t % 3).
#define ROWB   272
#define SLAB   34816
#define BAR_OFF (3 * 34816)
#define SMEM_TOTAL (3 * 34816 + 128)

// ============================================================================
// PTX helpers (no arch-suffixed features; ptxas target is plain sm_100)
// ============================================================================
__device__ __forceinline__ uint32_t smem_to_u32(const void* p) {
    uint32_t a;
    asm("{ .reg .u64 t; cvta.to.shared.u64 t, %1; cvt.u32.u64 %0, t; }" : "=r"(a) : "l"(p));
    return a;
}
__device__ __forceinline__ float ex2f_fast(float x) {
    float y; asm("ex2.approx.ftz.f32 %0, %1;" : "=f"(y) : "f"(x)); return y;
}
__device__ __forceinline__ float lg2f_fast(float x) {
    float y; asm("lg2.approx.f32 %0, %1;" : "=f"(y) : "f"(x)); return y;
}

#define LDSM_X4(r0, r1, r2, r3, addr) \
    asm volatile("ldmatrix.sync.aligned.m8n8.x4.shared.b16 {%0,%1,%2,%3}, [%4];" \
        : "=r"(r0), "=r"(r1), "=r"(r2), "=r"(r3) : "r"(addr))

#define MMA_BF16(d, a, b0, b1) \
    asm volatile("mma.sync.aligned.m16n8k16.row.col.f32.bf16.bf16.f32 " \
        "{%0,%1,%2,%3},{%4,%5,%6,%7},{%8,%9},{%0,%1,%2,%3};" \
        : "+f"((d)[0]), "+f"((d)[1]), "+f"((d)[2]), "+f"((d)[3]) \
        : "r"((a)[0]), "r"((a)[1]), "r"((a)[2]), "r"((a)[3]), "r"(b0), "r"(b1))

#define CP_ASYNC16(saddr, gptr) \
    asm volatile("cp.async.cg.shared.global [%0], [%1], 16;" :: "r"(saddr), "l"(gptr))
#define CP_COMMIT() asm volatile("cp.async.commit_group;")
#define CP_WAIT1()  asm volatile("cp.async.wait_group 1;")
// hardware arrival: fires on the mbarrier once all prior cp.async of this
// thread have completed (no wait instruction needed)
#define CP_ASYNC_MBAR_ARRIVE(a) \
    asm volatile("cp.async.mbarrier.arrive.noinc.shared.b64 [%0];" :: "r"(a) : "memory")

#define MBAR_INVAL(a) \
    asm volatile("mbarrier.inval.shared.b64 [%0];" :: "r"(a) : "memory")
#define MBAR_INIT(a, cnt) \
    asm volatile("mbarrier.init.shared.b64 [%0], %1;" :: "r"(a), "r"(cnt) : "memory")
#define MBAR_ARRIVE(a) \
    asm volatile("{.reg .b64 s; mbarrier.arrive.release.cta.shared::cta.b64 s, [%0];}" \
        :: "r"(a) : "memory")
#define MBAR_WAIT(a, par) do { \
    uint32_t _done; \
    asm volatile("{\n\t.reg .pred p;\n\t" \
        "mbarrier.try_wait.parity.acquire.cta.shared::cta.b64 p, [%1], %2;\n\t" \
        "selp.b32 %0, 1, 0, p;\n\t}" : "=r"(_done) : "r"(a), "r"(par) : "memory"); \
    while (!_done) { \
        asm volatile("{\n\t.reg .pred p;\n\t" \
            "mbarrier.try_wait.parity.acquire.cta.shared::cta.b64 p, [%1], %2;\n\t" \
            "selp.b32 %0, 1, 0, p;\n\t}" : "=r"(_done) : "r"(a), "r"(par) : "memory"); \
    } \
} while (0)

// warp-elected arrive: one smem atomic per warp instead of 32
#define WARP_ARRIVE(a, lane) do { \
    __syncwarp(); \
    if ((lane) == 0) MBAR_ARRIVE(a); \
} while (0)

// ============================================================================
// Kernel 1: normalize rows (fp32) -> bf16 (A scaled by C_EXP); zero state
// ============================================================================
__global__ void __launch_bounds__(256) normalize_kernel(const float* __restrict__ A,
                                                        const float* __restrict__ P) {
    int gid = blockIdx.x * blockDim.x + threadIdx.x;
    if (gid == 0) g_done = 0u;
    if (gid < NROWS) g_partS[gid] = 0.0f;
    int warp = gid >> 5;
    int lane = threadIdx.x & 31;
    if (warp >= 2 * NROWS) return;
    const float* src;
    __nv_bfloat16* dst;
    float extra;
    if (warp < NROWS) {
        src = A + (size_t)warp * DDIM; dst = g_Abf + (size_t)warp * DDIM; extra = C_EXP;
    } else {
        int r = warp - NROWS;
        src = P + (size_t)r * DDIM; dst = g_Pbf + (size_t)r * DDIM; extra = 1.0f;
    }
    float4 v = reinterpret_cast<const float4*>(src)[lane];
    float ss = v.x * v.x + v.y * v.y + v.z * v.z + v.w * v.w;
    #pragma unroll
    for (int o = 16; o > 0; o >>= 1) ss += __shfl_xor_sync(0xFFFFFFFFu, ss, o);
    float s = extra / fmaxf(sqrtf(ss), 1e-12f);
    __nv_bfloat162 h0 = __floats2bfloat162_rn(v.x * s, v.y * s);
    __nv_bfloat162 h1 = __floats2bfloat162_rn(v.z * s, v.w * s);
    reinterpret_cast<__nv_bfloat162*>(dst)[lane * 2 + 0] = h0;
    reinterpret_cast<__nv_bfloat162*>(dst)[lane * 2 + 1] = h1;
}

// ============================================================================
// cp.async loaders (272B padded rows)
// ============================================================================
__device__ __forceinline__ void cp_tile(uint32_t sbase, const __nv_bfloat16* gsrc, int tid) {
    const char* g = reinterpret_cast<const char*>(gsrc);
    #pragma unroll
    for (int i = 0; i < 8; i++) {
        int idx = tid + i * 256;          // 2048 chunks of 16B
        int row = idx >> 4;
        int c   = idx & 15;
        uint32_t s = sbase + row * ROWB + c * 16;
        CP_ASYNC16(s, g + idx * 16);
    }
}
// A super-tile: 256 rows -> slab1 (rows 0-127) + slab2 (rows 128-255)
__device__ __forceinline__ void cp_a_super(uint32_t slab1, uint32_t slab2,
                                           const __nv_bfloat16* gsrc, int tid) {
    const char* g = reinterpret_cast<const char*>(gsrc);
    #pragma unroll
    for (int i = 0; i < 16; i++) {
        int idx = tid + i * 256;          // 4096 chunks of 16B
        int row = idx >> 4;               // 0..255
        int c   = idx & 15;
        uint32_t base = (row < 128) ? slab1 : slab2;
        uint32_t s = base + (row & 127) * ROWB + c * 16;
        CP_ASYNC16(s, g + idx * 16);
    }
}

// ============================================================================
// Kernel 2: persistent fused GEMM + exp rowsum + diag + last-block reduction.
// 256-row SUPER-TILES: each warp = 32 rows x ALL 128 cols (8 chunks, 256 MMA
// per tile) -> per-tile pipeline overhead amortized over 2x the work.
// R13 pipeline otherwise: hw cp-completion full arrivals (count 256),
// warp-elected empties (count 8), chunk-7 epilogue deferred past producer.
// ============================================================================
__global__ void __launch_bounds__(256, 2) infonce_main_kernel(float* __restrict__ out) {
    extern __shared__ char smem[];
    uint32_t sb = smem_to_u32(smem);
    int tid = threadIdx.x;
    int lane = tid & 31;
    int w = tid >> 5;           // warp w -> rows w*32 .. w*32+31 of the super-tile

    int G = gridDim.x;
    int j0 = (int)(((long long)blockIdx.x * NJOBS) / G);
    int j1 = (int)(((long long)(blockIdx.x + 1) * NJOBS) / G);

    int g = lane >> 2;
    int tig = lane & 3;
    uint32_t b_lane_off = (uint32_t)(((lane & 7) + ((lane >> 4) << 3)) * ROWB
                                     + ((lane >> 3) & 1) * 16);
    const uint32_t bufoff[3] = {0, SLAB, 2 * SLAB};
    uint32_t bfull[3], bempty[3];
    #pragma unroll
    for (int i = 0; i < 3; i++) {
        bfull[i]  = sb + BAR_OFF + i * 8;
        bempty[i] = sb + BAR_OFF + 24 + i * 8;
    }

    int j = j0;
    while (j < j1) {
        int rb = j >> 7;            // super-row (0..63)
        int c0 = j & 127;
        int cend = min(j1 - (rb << 7), 128);
        int nt = cend - c0;

        __syncthreads();   // previous segment fully done with smem
        if (tid == 0) {
            #pragma unroll
            for (int i = 0; i < 3; i++) {
                MBAR_INVAL(bfull[i]);  MBAR_INIT(bfull[i], 256u);  // hw cp arrivals
                MBAR_INVAL(bempty[i]); MBAR_INIT(bempty[i], 8u);   // warp-elected
            }
        }
        __syncthreads();   // barriers initialized

        // Prologue: A (256 rows) -> slabs 1+2; tile c0 -> buf0 (hw arrival)
        cp_a_super(sb + bufoff[1], sb + bufoff[2],
                   g_Abf + (size_t)rb * SUPER * DDIM, tid);
        CP_COMMIT();                       // group: A
        cp_tile(sb + bufoff[0], g_Pbf + (size_t)c0 * TILE * DDIM, tid);
        CP_ASYNC_MBAR_ARRIVE(bfull[0]);
        CP_COMMIT();                       // group: tile 0
        CP_WAIT1();        // A group done locally (tile 0 may pend)
        __syncthreads();   // A visible to all threads

        // A fragments: 8 k-steps x 2 m16-frags x 4 regs (warp's 32 rows)
        uint32_t afrag[8][2][4];
        {
            uint32_t aslab = sb + ((w < 4) ? bufoff[1] : bufoff[2]);
            #pragma unroll
            for (int f = 0; f < 2; f++) {
                uint32_t a_addr = aslab + ((w & 3) * 32 + f * 16 + (lane & 15)) * ROWB
                                  + (lane >> 4) * 16;
                #pragma unroll
                for (int k = 0; k < 8; k++)
                    LDSM_X4(afrag[k][f][0], afrag[k][f][1], afrag[k][f][2], afrag[k][f][3],
                            a_addr + k * 32);
            }
        }
        WARP_ARRIVE(bempty[1], lane);   // frag-load = buffers 1&2 gen-0 consumption
        WARP_ARRIVE(bempty[2], lane);

        // produce tiles 1,2 into the freed A slabs (all warps share issuing)
        if (nt > 1) {
            MBAR_WAIT(bempty[1], 0u);
            cp_tile(sb + bufoff[1], g_Pbf + (size_t)(c0 + 1) * TILE * DDIM, tid);
            CP_ASYNC_MBAR_ARRIVE(bfull[1]);
        }
        if (nt > 2) {
            MBAR_WAIT(bempty[2], 0u);
            cp_tile(sb + bufoff[2], g_Pbf + (size_t)(c0 + 2) * TILE * DDIM, tid);
            CP_ASYNC_MBAR_ARRIVE(bfull[2]);
        }

        float S[4] = {0.f, 0.f, 0.f, 0.f};
        float d[4] = {0.f, 0.f, 0.f, 0.f};
        int my_diag_ct = 2 * rb + (w >> 2);   // global col-tile holding this warp's diag

        for (int t = 0; t < nt; t++) {
            int buf = t % 3;
            MBAR_WAIT(bfull[buf], (uint32_t)((t / 3) & 1));   // tile t landed

            uint32_t bbase = sb + bufoff[buf] + b_lane_off;
            int diag_t = (c0 + t == my_diag_ct);
            float pend[16];

            // chunks 0..6: MMA + inline epilogue
            #pragma unroll
            for (int c = 0; c < 7; c++) {
                float acc[16];
                #pragma unroll
                for (int q = 0; q < 16; q++) acc[q] = 0.0f;
                uint32_t bchunk = bbase + (uint32_t)(c * 16) * ROWB;
                #pragma unroll
                for (int k = 0; k < 8; k++) {
                    uint32_t b0, b1, b2, b3;
                    LDSM_X4(b0, b1, b2, b3, bchunk + k * 32);
                    MMA_BF16(acc + 0,  afrag[k][0], b0, b1);
                    MMA_BF16(acc + 4,  afrag[k][0], b2, b3);
                    MMA_BF16(acc + 8,  afrag[k][1], b0, b1);
                    MMA_BF16(acc + 12, afrag[k][1], b2, b3);
                }
                #pragma unroll
                for (int f = 0; f < 2; f++)
                    #pragma unroll
                    for (int nb = 0; nb < 2; nb++)
                        #pragma unroll
                        for (int q = 0; q < 4; q++) {
                            float v = acc[f * 8 + nb * 4 + q];
                            int hi = q >> 1;
                            S[f * 2 + hi] += ex2f_fast(v);
                            if (diag_t) {
                                int col_local = c * 16 + nb * 8 + tig * 2 + (q & 1);
                                int row_local = (w & 3) * 32 + f * 16 + hi * 8 + g;
                                if (col_local == row_local) d[f * 2 + hi] = v;
                            }
                        }
            }
            // chunk 7: MMA only; epilogue deferred past the producer ops
            {
                #pragma unroll
                for (int q = 0; q < 16; q++) pend[q] = 0.0f;
                uint32_t bchunk = bbase + (uint32_t)(7 * 16) * ROWB;
                #pragma unroll
                for (int k = 0; k < 8; k++) {
                    uint32_t b0, b1, b2, b3;
                    LDSM_X4(b0, b1, b2, b3, bchunk + k * 32);
                    MMA_BF16(pend + 0,  afrag[k][0], b0, b1);
                    MMA_BF16(pend + 4,  afrag[k][0], b2, b3);
                    MMA_BF16(pend + 8,  afrag[k][1], b0, b1);
                    MMA_BF16(pend + 12, afrag[k][1], b2, b3);
                }
            }
            WARP_ARRIVE(bempty[buf], lane);  // this warp's LDSMs of tile t done

            // producer (all warps share): tile u = t+3 into buffer u%3
            int u = t + 3;
            if (u < nt) {
                int ub = u % 3;
                uint32_t pe = (ub == 0) ? (uint32_t)((u / 3 + 1) & 1)
                                        : (uint32_t)((u / 3) & 1);
                MBAR_WAIT(bempty[ub], pe);
                cp_tile(sb + bufoff[ub], g_Pbf + (size_t)(c0 + u) * TILE * DDIM, tid);
                CP_ASYNC_MBAR_ARRIVE(bfull[ub]);
            }

            // deferred chunk-7 epilogue fills the gap before next wait(full)
            #pragma unroll
            for (int f = 0; f < 2; f++)
                #pragma unroll
                for (int nb = 0; nb < 2; nb++)
                    #pragma unroll
                    for (int q = 0; q < 4; q++) {
                        float v = pend[f * 8 + nb * 4 + q];
                        int hi = q >> 1;
                        S[f * 2 + hi] += ex2f_fast(v);
                        if (diag_t) {
                            int col_local = 7 * 16 + nb * 8 + tig * 2 + (q & 1);
                            int row_local = (w & 3) * 32 + f * 16 + hi * 8 + g;
                            if (col_local == row_local) d[f * 2 + hi] = v;
                        }
                    }
        }

        // segment flush: reduce across the 4 threads sharing each row
        #pragma unroll
        for (int i = 0; i < 4; i++) {
            S[i] += __shfl_xor_sync(0xFFFFFFFFu, S[i], 1);
            S[i] += __shfl_xor_sync(0xFFFFFFFFu, S[i], 2);
            d[i] += __shfl_xor_sync(0xFFFFFFFFu, d[i], 1);
            d[i] += __shfl_xor_sync(0xFFFFFFFFu, d[i], 2);
        }
        if (tig == 0) {
            int wrote_diag = (my_diag_ct >= c0) && (my_diag_ct < cend);
            #pragma unroll
            for (int i = 0; i < 4; i++) {
                int row = rb * SUPER + w * 32 + (i >> 1) * 16 + (i & 1) * 8 + g;
                atomicAdd(&g_partS[row], S[i]);
                if (wrote_diag) g_diagv[row] = d[i];
            }
        }
        j += nt;
    }

    // ---------------- last-block reduction: rowsum + finalize --------------
    __threadfence();
    __shared__ unsigned s_islast;
    __syncthreads();
    if (tid == 0) {
        unsigned t = atomicAdd(&g_done, 1u);
        s_islast = (t == (unsigned)(G - 1)) ? 1u : 0u;
    }
    __syncthreads();
    if (s_islast) {
        float sum = 0.0f;
        for (int row = tid; row < NROWS; row += 256) {
            float ps = __ldcg(&g_partS[row]);
            float dv = __ldcg(&g_diagv[row]);
            sum += (lg2f_fast(ps) - dv) * LN2;
        }
        #pragma unroll
        for (int o = 16; o > 0; o >>= 1) sum += __shfl_xor_sync(0xFFFFFFFFu, sum, o);
        __shared__ float red[8];
        if (lane == 0) red[w] = sum;
        __syncthreads();
        if (w == 0) {
            float s2 = (lane < 8) ? red[lane] : 0.0f;
            #pragma unroll
            for (int o = 4; o > 0; o >>= 1) s2 += __shfl_xor_sync(0xFFFFFFFFu, s2, o);
            if (lane == 0) out[0] = s2 * (1.0f / (float)NROWS);
        }
    }
}

// ============================================================================
// Launch
// ============================================================================
extern "C" void kernel_launch(void* const* d_in, const int* in_sizes, int n_in,
                              void* d_out, int out_size) {
    const float* A = (const float*)d_in[0];
    const float* P = (const float*)d_in[1];
    int nsm = 148;
    cudaDeviceGetAttribute(&nsm, cudaDevAttrMultiProcessorCount, 0);
    cudaFuncSetAttribute(infonce_main_kernel,
                         cudaFuncAttributeMaxDynamicSharedMemorySize, SMEM_TOTAL);
    normalize_kernel<<<(2 * NROWS) / 8, 256>>>(A, P);
    infonce_main_kernel<<<2 * nsm, 256, SMEM_TOTAL>>>((float*)d_out);
}